// round 2
// baseline (speedup 1.0000x reference)
#include <cuda_runtime.h>
#include <cstdint>

// Problem constants (fixed by reference: B=32, S=2048, D=512)
#define PB 32
#define PS 2048
#define PD 512
#define D4 (PD / 4)            // 128 float4 per (b,s) position

// Scratch: rank per (b,s). rank >= 0 iff mask is set; -1 otherwise.
__device__ int g_rank[PB * PS];

// ---------------------------------------------------------------------------
// Kernel 1: per-row inclusive scan of the mask (int32 elements) -> ranks.
// One block (1024 threads) per row; each thread handles 2 consecutive ints.
// ---------------------------------------------------------------------------
__global__ void __launch_bounds__(1024, 1)
rank_scan_kernel(const int* __restrict__ masks)
{
    const int b = blockIdx.x;
    const int* m = masks + (size_t)b * PS;
    const int t = threadIdx.x;            // 0..1023
    const int lane = t & 31;
    const int warp = t >> 5;

    // Load 2 mask ints per thread (int2 = coalesced 8B)
    const int i0 = 2 * t;
    const int2 mv = *reinterpret_cast<const int2*>(m + i0);
    const int m0 = (mv.x != 0) ? 1 : 0;
    const int m1 = (mv.y != 0) ? 1 : 0;
    const int s = m0 + m1;

    // Inclusive warp scan of per-thread sums
    int incl = s;
    #pragma unroll
    for (int off = 1; off < 32; off <<= 1) {
        int v = __shfl_up_sync(0xFFFFFFFFu, incl, off);
        if (lane >= off) incl += v;
    }

    // Warp totals -> block scan
    __shared__ int warp_tot[32];
    if (lane == 31) warp_tot[warp] = incl;
    __syncthreads();

    if (warp == 0) {
        int v = warp_tot[lane];
        int wincl = v;
        #pragma unroll
        for (int off = 1; off < 32; off <<= 1) {
            int u = __shfl_up_sync(0xFFFFFFFFu, wincl, off);
            if (lane >= off) wincl += u;
        }
        warp_tot[lane] = wincl - v;   // exclusive warp base
    }
    __syncthreads();

    const int base = warp_tot[warp];
    const int excl_thread = base + (incl - s);   // set-masks strictly before i0

    const int c0 = excl_thread + m0;  // inclusive count at i0
    const int c1 = c0 + m1;           // inclusive count at i0+1

    int2 rv;
    rv.x = m0 ? (c0 - 1) : -1;
    rv.y = m1 ? (c1 - 1) : -1;
    *reinterpret_cast<int2*>(g_rank + (size_t)b * PS + i0) = rv;
}

// ---------------------------------------------------------------------------
// Kernel 2: out = seqs + (rank >= 0 ? pe[rank] : 0), vectorized float4.
// 8,388,608 float4 elements total. row = idx >> 7 (128 float4 per position).
// ---------------------------------------------------------------------------
__global__ void __launch_bounds__(256, 8)
pe_add_kernel(const float4* __restrict__ seqs,
              const float4* __restrict__ pe,
              float4* __restrict__ out)
{
    const unsigned idx = blockIdx.x * blockDim.x + threadIdx.x; // < 2^23
    const unsigned row = idx >> 7;       // (b*S + s)
    const unsigned col = idx & 127;      // float4 column within D

    const int r = __ldg(&g_rank[row]);
    float4 v = __ldg(&seqs[idx]);
    if (r >= 0) {
        const float4 p = __ldg(&pe[(unsigned)r * D4 + col]);
        v.x += p.x; v.y += p.y; v.z += p.z; v.w += p.w;
    }
    out[idx] = v;
}

// ---------------------------------------------------------------------------
// Launch
// Inputs (metadata order): seqs [B,S,D] f32, masks [B,S] int32, pe [2048,D] f32
// Output: [B,S,D] f32
// ---------------------------------------------------------------------------
extern "C" void kernel_launch(void* const* d_in, const int* in_sizes, int n_in,
                              void* d_out, int out_size)
{
    const float* seqs  = (const float*)d_in[0];
    const int*   masks = (const int*)d_in[1];
    const float* pe    = (const float*)d_in[2];
    float*       out   = (float*)d_out;

    (void)in_sizes; (void)n_in; (void)out_size;

    // 1) rank scan: one block per row
    rank_scan_kernel<<<PB, 1024>>>(masks);

    // 2) fused add: 8,388,608 float4 -> 32768 blocks of 256 threads
    const unsigned total4 = (unsigned)PB * PS * D4;   // 8388608
    pe_add_kernel<<<total4 / 256, 256>>>(
        (const float4*)seqs, (const float4*)pe, (float4*)out);
}